// round 2
// baseline (speedup 1.0000x reference)
#include <cuda_runtime.h>
#include <cuda_bf16.h>
#include <math.h>

// Problem constants (fixed by the reference: B=4, S=2048, N_EMBD=1024, E=8, K=2, D_FF=4096)
#define T_TOK 8192
#define D_IN  1024
#define D_FF  4096
#define NE    8

// ---------------------------------------------------------------------------
// Scratch (__device__ globals: the only legal scratch under _HX_ENFORCE)
// ---------------------------------------------------------------------------
__device__ int   g_cnt[NE];            // tokens routed to expert e (this launch)
__device__ int   g_fill[NE];           // fill cursors for pair packing
__device__ int   g_off[NE];            // exclusive prefix of g_cnt
__device__ int   g_top[T_TOK * 2];     // per-token top-2 expert ids
__device__ float g_wt[T_TOK * 2];      // per-token top-2 routing weights
__device__ int   g_tok[T_TOK * 2];     // packed pair -> token index
__device__ float g_pw[T_TOK * 2];      // packed pair -> routing weight
// hidden activations for all 16384 (token, expert) pairs: 16384 x 4096 fp32 = 268 MB
__device__ float g_h[(size_t)T_TOK * 2 * D_FF];

// ---------------------------------------------------------------------------
// 0) zero the counters
// ---------------------------------------------------------------------------
__global__ void zero_counts_kernel() {
    int i = threadIdx.x;
    if (i < NE) { g_cnt[i] = 0; g_fill[i] = 0; }
}

// ---------------------------------------------------------------------------
// 1) router: logits = x @ Wr + br, top-2, softmax over the two survivors.
//    One warp per token.
// ---------------------------------------------------------------------------
__global__ void router_kernel(const float* __restrict__ x,
                              const float* __restrict__ Wr,
                              const float* __restrict__ br) {
    int gw   = (blockIdx.x * blockDim.x + threadIdx.x) >> 5;
    int lane = threadIdx.x & 31;
    if (gw >= T_TOK) return;

    const float* xr = x + (size_t)gw * D_IN;
    float acc[NE];
#pragma unroll
    for (int e = 0; e < NE; e++) acc[e] = 0.f;

    for (int d = lane; d < D_IN; d += 32) {
        float xv = xr[d];
        float4 a = *(const float4*)(Wr + d * NE);
        float4 b = *(const float4*)(Wr + d * NE + 4);
        acc[0] += xv * a.x; acc[1] += xv * a.y; acc[2] += xv * a.z; acc[3] += xv * a.w;
        acc[4] += xv * b.x; acc[5] += xv * b.y; acc[6] += xv * b.z; acc[7] += xv * b.w;
    }
#pragma unroll
    for (int e = 0; e < NE; e++) {
#pragma unroll
        for (int o = 16; o > 0; o >>= 1)
            acc[e] += __shfl_xor_sync(0xffffffffu, acc[e], o);
    }

    if (lane == 0) {
        float lg[NE];
#pragma unroll
        for (int e = 0; e < NE; e++) lg[e] = acc[e] + br[e];

        // top-2 with lowest-index-on-tie (matches jax.lax.top_k)
        int i0 = 0;
#pragma unroll
        for (int e = 1; e < NE; e++) if (lg[e] > lg[i0]) i0 = e;
        int i1 = (i0 == 0) ? 1 : 0;
#pragma unroll
        for (int e = 0; e < NE; e++) if (e != i0 && lg[e] > lg[i1]) i1 = e;

        // softmax over {v0, v1} (sparse logits are -inf elsewhere -> exp = 0)
        float ex  = expf(lg[i1] - lg[i0]);
        float inv = 1.0f / (1.0f + ex);

        g_top[2 * gw + 0] = i0;  g_top[2 * gw + 1] = i1;
        g_wt [2 * gw + 0] = inv; g_wt [2 * gw + 1] = ex * inv;
        atomicAdd(&g_cnt[i0], 1);
        atomicAdd(&g_cnt[i1], 1);
    }
}

// ---------------------------------------------------------------------------
// 2) tiny exclusive scan over 8 counters
// ---------------------------------------------------------------------------
__global__ void scan_kernel() {
    int s = 0;
    for (int e = 0; e < NE; e++) { g_off[e] = s; s += g_cnt[e]; }
}

// ---------------------------------------------------------------------------
// 3) pack (token, weight) pairs into per-expert contiguous segments.
//    Slot order within an expert is nondeterministic, but every pair's math is
//    row-independent and the final scatter is 2 commutative adds per element,
//    so the OUTPUT is deterministic.
// ---------------------------------------------------------------------------
__global__ void fill_kernel() {
    int t = blockIdx.x * blockDim.x + threadIdx.x;
    if (t >= T_TOK) return;
#pragma unroll
    for (int s = 0; s < 2; s++) {
        int e = g_top[2 * t + s];
        int p = g_off[e] + atomicAdd(&g_fill[e], 1);
        g_tok[p] = t;
        g_pw[p]  = g_wt[2 * t + s];
    }
}

// ---------------------------------------------------------------------------
// 4) FFN layer 1: h = relu(gather(x) @ W1[e] + b1[e])   [cnt_e x 4096]
//    Classic 128x128x8 SGEMM tile, 256 threads, 8x8 per-thread microtile.
// ---------------------------------------------------------------------------
__global__ __launch_bounds__(256, 1)
void ffn1_kernel(const float* __restrict__ x,
                 const float* __restrict__ W1,
                 const float* __restrict__ b1) {
    const int e   = blockIdx.z;
    const int cnt = g_cnt[e];
    const int m0  = blockIdx.y * 128;
    if (m0 >= cnt) return;
    const int n0   = blockIdx.x * 128;
    const int base = g_off[e];

    __shared__ float As[8][128];
    __shared__ float Bs[8][128];

    const float* W = W1 + (size_t)e * D_IN * D_FF;
    const int t    = threadIdx.x;
    const int aRow = t >> 1;            // 0..127
    const int aK   = (t & 1) * 4;       // 0 or 4
    const int bK   = t >> 5;            // 0..7
    const int bN   = (t & 31) * 4;      // 0..124

    const int mrow = m0 + aRow;
    const int tok  = g_tok[base + min(mrow, cnt - 1)];
    const float* ap = x + (size_t)tok * D_IN;
    const float* bp = W + (size_t)bK * D_FF + n0 + bN;

    const int tr = (t >> 4) * 8;        // row base of microtile
    const int tc = (t & 15) * 8;        // col base of microtile

    float acc[8][8];
#pragma unroll
    for (int i = 0; i < 8; i++)
#pragma unroll
        for (int j = 0; j < 8; j++) acc[i][j] = 0.f;

    for (int k0 = 0; k0 < D_IN; k0 += 8) {
        float4 av = *(const float4*)(ap + k0 + aK);
        float4 bv = *(const float4*)(bp + (size_t)k0 * D_FF);
        As[aK + 0][aRow] = av.x; As[aK + 1][aRow] = av.y;
        As[aK + 2][aRow] = av.z; As[aK + 3][aRow] = av.w;
        *(float4*)&Bs[bK][bN] = bv;
        __syncthreads();
#pragma unroll
        for (int k = 0; k < 8; k++) {
            float rm[8], rn[8];
            *(float4*)&rm[0] = *(const float4*)&As[k][tr];
            *(float4*)&rm[4] = *(const float4*)&As[k][tr + 4];
            *(float4*)&rn[0] = *(const float4*)&Bs[k][tc];
            *(float4*)&rn[4] = *(const float4*)&Bs[k][tc + 4];
#pragma unroll
            for (int i = 0; i < 8; i++)
#pragma unroll
                for (int j = 0; j < 8; j++)
                    acc[i][j] += rm[i] * rn[j];
        }
        __syncthreads();
    }

    float bias[8];
    *(float4*)&bias[0] = *(const float4*)(b1 + (size_t)e * D_FF + n0 + tc);
    *(float4*)&bias[4] = *(const float4*)(b1 + (size_t)e * D_FF + n0 + tc + 4);

#pragma unroll
    for (int i = 0; i < 8; i++) {
        int m = m0 + tr + i;
        if (m >= cnt) break;
        float* hp = g_h + (size_t)(base + m) * D_FF + n0 + tc;
        float4 v0, v1;
        v0.x = fmaxf(acc[i][0] + bias[0], 0.f);
        v0.y = fmaxf(acc[i][1] + bias[1], 0.f);
        v0.z = fmaxf(acc[i][2] + bias[2], 0.f);
        v0.w = fmaxf(acc[i][3] + bias[3], 0.f);
        v1.x = fmaxf(acc[i][4] + bias[4], 0.f);
        v1.y = fmaxf(acc[i][5] + bias[5], 0.f);
        v1.z = fmaxf(acc[i][6] + bias[6], 0.f);
        v1.w = fmaxf(acc[i][7] + bias[7], 0.f);
        *(float4*)(hp)     = v0;
        *(float4*)(hp + 4) = v1;
    }
}

// ---------------------------------------------------------------------------
// 5) FFN layer 2: out[tok] += w * (h @ W2[e] + b2[e])
//    Same tile shape; epilogue scatters with atomicAdd (exactly 2 adds/element).
// ---------------------------------------------------------------------------
__global__ __launch_bounds__(256, 1)
void ffn2_kernel(const float* __restrict__ W2,
                 const float* __restrict__ b2,
                 float* __restrict__ out) {
    const int e   = blockIdx.z;
    const int cnt = g_cnt[e];
    const int m0  = blockIdx.y * 128;
    if (m0 >= cnt) return;
    const int n0   = blockIdx.x * 128;
    const int base = g_off[e];

    __shared__ float As[8][128];
    __shared__ float Bs[8][128];

    const float* W = W2 + (size_t)e * D_FF * D_IN;
    const int t    = threadIdx.x;
    const int aRow = t >> 1;
    const int aK   = (t & 1) * 4;
    const int bK   = t >> 5;
    const int bN   = (t & 31) * 4;

    const int mrow = min(m0 + aRow, cnt - 1);
    const float* ap = g_h + (size_t)(base + mrow) * D_FF;
    const float* bp = W + (size_t)bK * D_IN + n0 + bN;

    const int tr = (t >> 4) * 8;
    const int tc = (t & 15) * 8;

    float acc[8][8];
#pragma unroll
    for (int i = 0; i < 8; i++)
#pragma unroll
        for (int j = 0; j < 8; j++) acc[i][j] = 0.f;

    for (int k0 = 0; k0 < D_FF; k0 += 8) {
        float4 av = *(const float4*)(ap + k0 + aK);
        float4 bv = *(const float4*)(bp + (size_t)k0 * D_IN);
        As[aK + 0][aRow] = av.x; As[aK + 1][aRow] = av.y;
        As[aK + 2][aRow] = av.z; As[aK + 3][aRow] = av.w;
        *(float4*)&Bs[bK][bN] = bv;
        __syncthreads();
#pragma unroll
        for (int k = 0; k < 8; k++) {
            float rm[8], rn[8];
            *(float4*)&rm[0] = *(const float4*)&As[k][tr];
            *(float4*)&rm[4] = *(const float4*)&As[k][tr + 4];
            *(float4*)&rn[0] = *(const float4*)&Bs[k][tc];
            *(float4*)&rn[4] = *(const float4*)&Bs[k][tc + 4];
#pragma unroll
            for (int i = 0; i < 8; i++)
#pragma unroll
                for (int j = 0; j < 8; j++)
                    acc[i][j] += rm[i] * rn[j];
        }
        __syncthreads();
    }

    float bias[8];
    *(float4*)&bias[0] = *(const float4*)(b2 + (size_t)e * D_IN + n0 + tc);
    *(float4*)&bias[4] = *(const float4*)(b2 + (size_t)e * D_IN + n0 + tc + 4);

#pragma unroll
    for (int i = 0; i < 8; i++) {
        int m = m0 + tr + i;
        if (m >= cnt) break;
        int   tok = g_tok[base + m];
        float w   = g_pw[base + m];
        float* op = out + (size_t)tok * D_IN + n0 + tc;
#pragma unroll
        for (int j = 0; j < 8; j++)
            atomicAdd(&op[j], w * (acc[i][j] + bias[j]));
    }
}

// ---------------------------------------------------------------------------
// launch
// ---------------------------------------------------------------------------
extern "C" void kernel_launch(void* const* d_in, const int* in_sizes, int n_in,
                              void* d_out, int out_size) {
    const float* x   = (const float*)d_in[0];
    const float* Wr  = (const float*)d_in[1];
    const float* br  = (const float*)d_in[2];
    const float* W1  = (const float*)d_in[3];
    const float* b1  = (const float*)d_in[4];
    const float* W2  = (const float*)d_in[5];
    const float* b2  = (const float*)d_in[6];
    float*       out = (float*)d_out;

    cudaMemsetAsync(out, 0, (size_t)out_size * sizeof(float));
    zero_counts_kernel<<<1, 32>>>();
    router_kernel<<<T_TOK / 8, 256>>>(x, Wr, br);   // 8 warps/block, 1 warp/token
    scan_kernel<<<1, 1>>>();
    fill_kernel<<<T_TOK / 256, 256>>>();
    ffn1_kernel<<<dim3(D_FF / 128, T_TOK / 128, NE), 256>>>(x, W1, b1);
    ffn2_kernel<<<dim3(D_IN / 128, T_TOK / 128, NE), 256>>>(W2, b2, out);
}

// round 5
// speedup vs baseline: 1.8675x; 1.8675x over previous
#include <cuda_runtime.h>
#include <cuda_bf16.h>
#include <math.h>
#include <stdint.h>

// Problem constants: B=4, S=2048, N_EMBD=1024, E=8, K=2, D_FF=4096
#define T_TOK 8192
#define D_IN  1024
#define D_FF  4096
#define NE    8

// ---------------------------------------------------------------------------
// Scratch (__device__ globals only)
// ---------------------------------------------------------------------------
__device__ int      g_cnt[NE];
__device__ int      g_fill[NE];
__device__ int      g_off[NE];
__device__ int      g_top[T_TOK * 2];
__device__ float    g_wt[T_TOK * 2];
__device__ int      g_tok[T_TOK * 2];
__device__ float    g_pw[T_TOK * 2];
// hidden acts, PRE-SPLIT: each element = (bf16_hi << 16) | bf16_lo  (268 MB)
__device__ uint32_t g_h[(size_t)T_TOK * 2 * D_FF];

// ---------------------------------------------------------------------------
// Portable PTX helpers (sm_80+: mma.sync + ldmatrix — no tcgen05!)
// ---------------------------------------------------------------------------
__device__ __forceinline__ uint32_t smem_u32(const void* p) {
    uint32_t a;
    asm("{ .reg .u64 t; cvta.to.shared.u64 t, %1; cvt.u32.u64 %0, t; }"
        : "=r"(a) : "l"(p));
    return a;
}

__device__ __forceinline__ void ldsm4(uint32_t* r, uint32_t addr) {
    asm volatile("ldmatrix.sync.aligned.m8n8.x4.shared.b16 {%0,%1,%2,%3}, [%4];"
        : "=r"(r[0]), "=r"(r[1]), "=r"(r[2]), "=r"(r[3]) : "r"(addr));
}
__device__ __forceinline__ void ldsm4t(uint32_t* r, uint32_t addr) {
    asm volatile("ldmatrix.sync.aligned.m8n8.x4.trans.shared.b16 {%0,%1,%2,%3}, [%4];"
        : "=r"(r[0]), "=r"(r[1]), "=r"(r[2]), "=r"(r[3]) : "r"(addr));
}
__device__ __forceinline__ void mma16816(float* d, const uint32_t* a,
                                         uint32_t b0, uint32_t b1) {
    asm volatile(
        "mma.sync.aligned.m16n8k16.row.col.f32.bf16.bf16.f32 "
        "{%0,%1,%2,%3}, {%4,%5,%6,%7}, {%8,%9}, {%0,%1,%2,%3};"
        : "+f"(d[0]), "+f"(d[1]), "+f"(d[2]), "+f"(d[3])
        : "r"(a[0]), "r"(a[1]), "r"(a[2]), "r"(a[3]), "r"(b0), "r"(b1));
}

// bf16 hi/lo split of a float4 -> two packed bf16x2 words each
__device__ __forceinline__ void bf16_split4(float4 v, uint2& hi, uint2& lo) {
    __nv_bfloat16 h0 = __float2bfloat16(v.x);
    __nv_bfloat16 h1 = __float2bfloat16(v.y);
    __nv_bfloat16 h2 = __float2bfloat16(v.z);
    __nv_bfloat16 h3 = __float2bfloat16(v.w);
    hi.x = ((uint32_t)__bfloat16_as_ushort(h1) << 16) | __bfloat16_as_ushort(h0);
    hi.y = ((uint32_t)__bfloat16_as_ushort(h3) << 16) | __bfloat16_as_ushort(h2);
    __nv_bfloat16 l0 = __float2bfloat16(v.x - __bfloat162float(h0));
    __nv_bfloat16 l1 = __float2bfloat16(v.y - __bfloat162float(h1));
    __nv_bfloat16 l2 = __float2bfloat16(v.z - __bfloat162float(h2));
    __nv_bfloat16 l3 = __float2bfloat16(v.w - __bfloat162float(h3));
    lo.x = ((uint32_t)__bfloat16_as_ushort(l1) << 16) | __bfloat16_as_ushort(l0);
    lo.y = ((uint32_t)__bfloat16_as_ushort(l3) << 16) | __bfloat16_as_ushort(l2);
}

// split one fp32 into packed (hi<<16)|lo (for g_h)
__device__ __forceinline__ uint32_t pack_split(float v) {
    __nv_bfloat16 h = __float2bfloat16(v);
    __nv_bfloat16 l = __float2bfloat16(v - __bfloat162float(h));
    return ((uint32_t)__bfloat16_as_ushort(h) << 16) | __bfloat16_as_ushort(l);
}

// ---------------------------------------------------------------------------
// SMEM: two 32 KB buffers. Per buffer:
//   [0,8192)      A_hi : 128 rows x 32 bf16 (64B rows, swizzled)
//   [8192,16384)  A_lo
//   [16384,24576) B_hi : 4 subtiles [32k x 32n] (64B rows, swizzled)
//   [24576,32768) B_lo
// Swizzle (64B rows, 4x16B chunks): chunk' = chunk ^ ((row>>1)&3)
// -> conflict-free for both STS.128 fills and 8-row ldmatrix phases.
// ---------------------------------------------------------------------------
#define BUF_BYTES 32768
#define SMEM_BYTES (2 * BUF_BYTES)
#define OFF_AHI 0
#define OFF_ALO 8192
#define OFF_BHI 16384
#define OFF_BLO 24576

__device__ __forceinline__ int swz(int row, int chunk) {
    return row * 64 + ((chunk ^ ((row >> 1) & 3)) << 4);
}

// ---------------------------------------------------------------------------
// bf16x3 HMMA GEMM for both FFN layers.
//  GATHER=true : A = x[g_tok[...]] (fp32, split on load);
//                epilogue relu+bias -> g_h (packed hi/lo)        K=1024
//  GATHER=false: A = g_h (pre-split packed);
//                epilogue bias, *w -> atomicAdd out              K=4096
// CTA tile 128x128, K-chunk 32, 256 threads (8 warps, 64x32 warp tiles).
// ---------------------------------------------------------------------------
template<int K_TOTAL, int B_STRIDE, bool GATHER>
__global__ __launch_bounds__(256)
void moe_mma_kernel(const float* __restrict__ A_f,
                    const float* __restrict__ W,
                    const float* __restrict__ bias,
                    float* __restrict__ out) {
    const int e   = blockIdx.z;
    const int cnt = g_cnt[e];
    const int m0  = blockIdx.y * 128;
    if (m0 >= cnt) return;
    const int n0   = blockIdx.x * 128;
    const int base = g_off[e];

    extern __shared__ char smem[];
    const uint32_t sb = smem_u32(smem);
    const int t    = threadIdx.x;
    const int lane = t & 31;
    const int wid  = t >> 5;
    const int wm   = wid >> 2;     // 0..1
    const int wn   = wid & 3;      // 0..3

    // ---- staging assignments -------------------------------------------
    // A: 2 threads/row: rowA = t>>1 (0..127), 16 consecutive k from colA
    const int rowA = t >> 1;
    const int colA = (t & 1) * 16;
    const float*    a_f = nullptr;
    const uint32_t* a_u = nullptr;
    {
        int m = min(m0 + rowA, cnt - 1);
        if (GATHER) a_f = A_f + (size_t)g_tok[base + m] * D_IN;
        else        a_u = g_h + (size_t)(base + m) * D_FF;
    }
    // B: 8 threads/row: kB = t>>3 (0..31), 16 consecutive n from nb
    const int kB = t >> 3;
    const int nb = (t & 7) * 16;
    const int bsub = nb >> 5;            // which 32-wide n subtile
    const int cB0  = ((nb & 31) >> 3);   // first 16B chunk within subtile (0 or 2)
    const float* Wb = W + (size_t)e * K_TOTAL * B_STRIDE + n0;

    float4 stA[4]; uint4 stAu[4]; float4 stB[4];

    auto load_stage = [&](int k0) {
#pragma unroll
        for (int i = 0; i < 4; i++) {
            if (GATHER) stA[i] = *(const float4*)(a_f + k0 + colA + 4 * i);
            else        stAu[i] = *(const uint4*)(a_u + k0 + colA + 4 * i);
            stB[i] = *(const float4*)(Wb + (size_t)(k0 + kB) * B_STRIDE + nb + 4 * i);
        }
    };

    auto store_stage = [&](int buf) {
        char* s = smem + buf * BUF_BYTES;
        // ---- A ----
        uint4 H[2], L[2];
        if (GATHER) {
#pragma unroll
            for (int p = 0; p < 2; p++) {
                uint2 h0, l0, h1, l1;
                bf16_split4(stA[2 * p + 0], h0, l0);
                bf16_split4(stA[2 * p + 1], h1, l1);
                H[p] = make_uint4(h0.x, h0.y, h1.x, h1.y);
                L[p] = make_uint4(l0.x, l0.y, l1.x, l1.y);
            }
        } else {
#pragma unroll
            for (int p = 0; p < 2; p++) {
                uint4 u0 = stAu[2 * p + 0], u1 = stAu[2 * p + 1];
                H[p] = make_uint4(__byte_perm(u0.x, u0.y, 0x7632),
                                  __byte_perm(u0.z, u0.w, 0x7632),
                                  __byte_perm(u1.x, u1.y, 0x7632),
                                  __byte_perm(u1.z, u1.w, 0x7632));
                L[p] = make_uint4(__byte_perm(u0.x, u0.y, 0x5410),
                                  __byte_perm(u0.z, u0.w, 0x5410),
                                  __byte_perm(u1.x, u1.y, 0x5410),
                                  __byte_perm(u1.z, u1.w, 0x5410));
            }
        }
        const int cA0 = (t & 1) * 2;
#pragma unroll
        for (int p = 0; p < 2; p++) {
            int o = swz(rowA, cA0 + p);
            *(uint4*)(s + OFF_AHI + o) = H[p];
            *(uint4*)(s + OFF_ALO + o) = L[p];
        }
        // ---- B ----
#pragma unroll
        for (int p = 0; p < 2; p++) {
            uint2 h0, l0, h1, l1;
            bf16_split4(stB[2 * p + 0], h0, l0);
            bf16_split4(stB[2 * p + 1], h1, l1);
            int o = bsub * 2048 + swz(kB, cB0 + p);
            *(uint4*)(s + OFF_BHI + o) = make_uint4(h0.x, h0.y, h1.x, h1.y);
            *(uint4*)(s + OFF_BLO + o) = make_uint4(l0.x, l0.y, l1.x, l1.y);
        }
    };

    float acc[4][4][4];
#pragma unroll
    for (int i = 0; i < 4; i++)
#pragma unroll
        for (int j = 0; j < 4; j++)
#pragma unroll
            for (int r = 0; r < 4; r++) acc[i][j][r] = 0.f;

    const int ml = lane & 15;
    const int chhi = lane >> 4;

    auto mma_stage = [&](int buf) {
        const uint32_t sbuf = sb + buf * BUF_BYTES;
#pragma unroll
        for (int ks = 0; ks < 2; ks++) {
            uint32_t ah[4][4], al[4][4], bh[2][4], bl[2][4];
#pragma unroll
            for (int i = 0; i < 4; i++) {
                int m = wm * 64 + i * 16 + ml;
                int cc = (ks * 2 + chhi) ^ ((m >> 1) & 3);
                uint32_t ad = sbuf + m * 64 + cc * 16;
                ldsm4(ah[i], ad + OFF_AHI);
                ldsm4(al[i], ad + OFF_ALO);
            }
#pragma unroll
            for (int p = 0; p < 2; p++) {
                int k = ks * 16 + ml;
                int cc = (p * 2 + chhi) ^ ((k >> 1) & 3);
                uint32_t bd = sbuf + wn * 2048 + k * 64 + cc * 16;
                ldsm4t(bh[p], bd + OFF_BHI);
                ldsm4t(bl[p], bd + OFF_BLO);
            }
#pragma unroll
            for (int i = 0; i < 4; i++)
#pragma unroll
                for (int j = 0; j < 4; j++) {
                    uint32_t b0h = bh[j >> 1][(j & 1) * 2];
                    uint32_t b1h = bh[j >> 1][(j & 1) * 2 + 1];
                    uint32_t b0l = bl[j >> 1][(j & 1) * 2];
                    uint32_t b1l = bl[j >> 1][(j & 1) * 2 + 1];
                    mma16816(acc[i][j], ah[i], b0h, b1h);   // hi*hi
                    mma16816(acc[i][j], ah[i], b0l, b1l);   // hi*lo
                    mma16816(acc[i][j], al[i], b0h, b1h);   // lo*hi
                }
        }
    };

    // ---- pipelined main loop -------------------------------------------
    const int NCH = K_TOTAL / 32;
    load_stage(0);
    store_stage(0);
    __syncthreads();
    for (int ch = 0; ch < NCH; ch++) {
        if (ch + 1 < NCH) load_stage((ch + 1) * 32);
        mma_stage(ch & 1);
        if (ch + 1 < NCH) {
            store_stage((ch + 1) & 1);
            __syncthreads();
        }
    }

    // ---- epilogue -------------------------------------------------------
    const float* be = bias + (size_t)e * B_STRIDE;
#pragma unroll
    for (int i = 0; i < 4; i++) {
        int mA = m0 + wm * 64 + i * 16 + (lane >> 2);
#pragma unroll
        for (int half = 0; half < 2; half++) {     // rows mA and mA+8
            int m = mA + half * 8;
            if (m >= cnt) continue;
            uint32_t* hp = nullptr;
            float*    op = nullptr;
            float     rw = 0.f;
            if (GATHER) {
                hp = g_h + (size_t)(base + m) * D_FF;
            } else {
                op = out + (size_t)g_tok[base + m] * D_IN;
                rw = g_pw[base + m];
            }
#pragma unroll
            for (int j = 0; j < 4; j++) {
                int n = n0 + wn * 32 + j * 8 + (lane & 3) * 2;
                float v0 = acc[i][j][half * 2 + 0] + be[n];
                float v1 = acc[i][j][half * 2 + 1] + be[n + 1];
                if (GATHER) {
                    uint2 pk;
                    pk.x = pack_split(fmaxf(v0, 0.f));
                    pk.y = pack_split(fmaxf(v1, 0.f));
                    *(uint2*)(hp + n) = pk;
                } else {
                    atomicAdd(&op[n],     rw * v0);
                    atomicAdd(&op[n + 1], rw * v1);
                }
            }
        }
    }
}

// ---------------------------------------------------------------------------
// Router / packing (unchanged from the passing fp32 baseline)
// ---------------------------------------------------------------------------
__global__ void zero_counts_kernel() {
    int i = threadIdx.x;
    if (i < NE) { g_cnt[i] = 0; g_fill[i] = 0; }
}

__global__ void router_kernel(const float* __restrict__ x,
                              const float* __restrict__ Wr,
                              const float* __restrict__ br) {
    int gw   = (blockIdx.x * blockDim.x + threadIdx.x) >> 5;
    int lane = threadIdx.x & 31;
    if (gw >= T_TOK) return;

    const float* xr = x + (size_t)gw * D_IN;
    float acc[NE];
#pragma unroll
    for (int e = 0; e < NE; e++) acc[e] = 0.f;

    for (int d = lane; d < D_IN; d += 32) {
        float xv = xr[d];
        float4 a = *(const float4*)(Wr + d * NE);
        float4 b = *(const float4*)(Wr + d * NE + 4);
        acc[0] += xv * a.x; acc[1] += xv * a.y; acc[2] += xv * a.z; acc[3] += xv * a.w;
        acc[4] += xv * b.x; acc[5] += xv * b.y; acc[6] += xv * b.z; acc[7] += xv * b.w;
    }
#pragma unroll
    for (int e = 0; e < NE; e++) {
#pragma unroll
        for (int o = 16; o > 0; o >>= 1)
            acc[e] += __shfl_xor_sync(0xffffffffu, acc[e], o);
    }
    if (lane == 0) {
        float lg[NE];
#pragma unroll
        for (int e = 0; e < NE; e++) lg[e] = acc[e] + br[e];
        int i0 = 0;
#pragma unroll
        for (int e = 1; e < NE; e++) if (lg[e] > lg[i0]) i0 = e;
        int i1 = (i0 == 0) ? 1 : 0;
#pragma unroll
        for (int e = 0; e < NE; e++) if (e != i0 && lg[e] > lg[i1]) i1 = e;
        float ex  = expf(lg[i1] - lg[i0]);
        float inv = 1.0f / (1.0f + ex);
        g_top[2 * gw + 0] = i0;  g_top[2 * gw + 1] = i1;
        g_wt [2 * gw + 0] = inv; g_wt [2 * gw + 1] = ex * inv;
        atomicAdd(&g_cnt[i0], 1);
        atomicAdd(&g_cnt[i1], 1);
    }
}

__global__ void scan_kernel() {
    int s = 0;
    for (int e = 0; e < NE; e++) { g_off[e] = s; s += g_cnt[e]; }
}

__global__ void fill_kernel() {
    int t = blockIdx.x * blockDim.x + threadIdx.x;
    if (t >= T_TOK) return;
#pragma unroll
    for (int s = 0; s < 2; s++) {
        int e = g_top[2 * t + s];
        int p = g_off[e] + atomicAdd(&g_fill[e], 1);
        g_tok[p] = t;
        g_pw[p]  = g_wt[2 * t + s];
    }
}

// ---------------------------------------------------------------------------
// launch
// ---------------------------------------------------------------------------
extern "C" void kernel_launch(void* const* d_in, const int* in_sizes, int n_in,
                              void* d_out, int out_size) {
    const float* x   = (const float*)d_in[0];
    const float* Wr  = (const float*)d_in[1];
    const float* br  = (const float*)d_in[2];
    const float* W1  = (const float*)d_in[3];
    const float* b1  = (const float*)d_in[4];
    const float* W2  = (const float*)d_in[5];
    const float* b2  = (const float*)d_in[6];
    float*       out = (float*)d_out;

    cudaFuncSetAttribute(moe_mma_kernel<1024, 4096, true>,
                         cudaFuncAttributeMaxDynamicSharedMemorySize, SMEM_BYTES);
    cudaFuncSetAttribute(moe_mma_kernel<4096, 1024, false>,
                         cudaFuncAttributeMaxDynamicSharedMemorySize, SMEM_BYTES);

    cudaMemsetAsync(out, 0, (size_t)out_size * sizeof(float));
    zero_counts_kernel<<<1, 32>>>();
    router_kernel<<<T_TOK / 8, 256>>>(x, Wr, br);
    scan_kernel<<<1, 1>>>();
    fill_kernel<<<T_TOK / 256, 256>>>();
    // FFN1: h = relu(x_g @ W1 + b1) -> g_h (packed hi/lo); K=1024
    moe_mma_kernel<1024, 4096, true>
        <<<dim3(D_FF / 128, T_TOK / 128, NE), 256, SMEM_BYTES>>>(x, W1, b1, out);
    // FFN2: out += w * (h @ W2 + b2); K=4096
    moe_mma_kernel<4096, 1024, false>
        <<<dim3(D_IN / 128, T_TOK / 128, NE), 256, SMEM_BYTES>>>(nullptr, W2, b2, out);
}

// round 6
// speedup vs baseline: 2.4862x; 1.3313x over previous
#include <cuda_runtime.h>
#include <cuda_bf16.h>
#include <math.h>
#include <stdint.h>

// Problem constants: B=4, S=2048, N_EMBD=1024, E=8, K=2, D_FF=4096
#define T_TOK 8192
#define D_IN  1024
#define D_FF  4096
#define NE    8

// ---------------------------------------------------------------------------
// Scratch (__device__ globals only)
// ---------------------------------------------------------------------------
__device__ int      g_cnt[NE];
__device__ int      g_fill[NE];
__device__ int      g_off[NE];
__device__ int      g_top[T_TOK * 2];
__device__ float    g_wt[T_TOK * 2];
__device__ int      g_tok[T_TOK * 2];
__device__ float    g_pw[T_TOK * 2];

// Pre-split bf16 planes (hi + lo) for everything the GEMMs touch.
__device__ __nv_bfloat16 g_xhi[(size_t)T_TOK * D_IN];
__device__ __nv_bfloat16 g_xlo[(size_t)T_TOK * D_IN];
__device__ __nv_bfloat16 g_w1hi[(size_t)NE * D_IN * D_FF];
__device__ __nv_bfloat16 g_w1lo[(size_t)NE * D_IN * D_FF];
__device__ __nv_bfloat16 g_w2hi[(size_t)NE * D_FF * D_IN];
__device__ __nv_bfloat16 g_w2lo[(size_t)NE * D_FF * D_IN];
__device__ __nv_bfloat16 g_hhi[(size_t)T_TOK * 2 * D_FF];
__device__ __nv_bfloat16 g_hlo[(size_t)T_TOK * 2 * D_FF];

// ---------------------------------------------------------------------------
// Portable PTX helpers (sm_80+ only: mma.sync, ldmatrix, cp.async)
// ---------------------------------------------------------------------------
__device__ __forceinline__ uint32_t smem_u32(const void* p) {
    uint32_t a;
    asm("{ .reg .u64 t; cvta.to.shared.u64 t, %1; cvt.u32.u64 %0, t; }"
        : "=r"(a) : "l"(p));
    return a;
}
__device__ __forceinline__ void ldsm4(uint32_t* r, uint32_t addr) {
    asm volatile("ldmatrix.sync.aligned.m8n8.x4.shared.b16 {%0,%1,%2,%3}, [%4];"
        : "=r"(r[0]), "=r"(r[1]), "=r"(r[2]), "=r"(r[3]) : "r"(addr));
}
__device__ __forceinline__ void ldsm4t(uint32_t* r, uint32_t addr) {
    asm volatile("ldmatrix.sync.aligned.m8n8.x4.trans.shared.b16 {%0,%1,%2,%3}, [%4];"
        : "=r"(r[0]), "=r"(r[1]), "=r"(r[2]), "=r"(r[3]) : "r"(addr));
}
__device__ __forceinline__ void mma16816(float* d, const uint32_t* a,
                                         uint32_t b0, uint32_t b1) {
    asm volatile(
        "mma.sync.aligned.m16n8k16.row.col.f32.bf16.bf16.f32 "
        "{%0,%1,%2,%3}, {%4,%5,%6,%7}, {%8,%9}, {%0,%1,%2,%3};"
        : "+f"(d[0]), "+f"(d[1]), "+f"(d[2]), "+f"(d[3])
        : "r"(a[0]), "r"(a[1]), "r"(a[2]), "r"(a[3]), "r"(b0), "r"(b1));
}
__device__ __forceinline__ void cp16(uint32_t dst, const void* src) {
    asm volatile("cp.async.cg.shared.global [%0], [%1], 16;"
                 :: "r"(dst), "l"(src) : "memory");
}
__device__ __forceinline__ void cp_commit() {
    asm volatile("cp.async.commit_group;" ::: "memory");
}
template<int N> __device__ __forceinline__ void cp_wait() {
    asm volatile("cp.async.wait_group %0;" :: "n"(N) : "memory");
}

// bf16 hi/lo split of a float4 -> two packed bf16x2 words each
__device__ __forceinline__ void bf16_split4(float4 v, uint2& hi, uint2& lo) {
    __nv_bfloat16 h0 = __float2bfloat16(v.x);
    __nv_bfloat16 h1 = __float2bfloat16(v.y);
    __nv_bfloat16 h2 = __float2bfloat16(v.z);
    __nv_bfloat16 h3 = __float2bfloat16(v.w);
    hi.x = ((uint32_t)__bfloat16_as_ushort(h1) << 16) | __bfloat16_as_ushort(h0);
    hi.y = ((uint32_t)__bfloat16_as_ushort(h3) << 16) | __bfloat16_as_ushort(h2);
    __nv_bfloat16 l0 = __float2bfloat16(v.x - __bfloat162float(h0));
    __nv_bfloat16 l1 = __float2bfloat16(v.y - __bfloat162float(h1));
    __nv_bfloat16 l2 = __float2bfloat16(v.z - __bfloat162float(h2));
    __nv_bfloat16 l3 = __float2bfloat16(v.w - __bfloat162float(h3));
    lo.x = ((uint32_t)__bfloat16_as_ushort(l1) << 16) | __bfloat16_as_ushort(l0);
    lo.y = ((uint32_t)__bfloat16_as_ushort(l3) << 16) | __bfloat16_as_ushort(l2);
}

// ---------------------------------------------------------------------------
// SMEM: two 32 KB stages, layout IDENTICAL to the passing R5 kernel:
//   [0,8192)      A_hi : 128 rows x 32 bf16 (64B rows, swizzled)
//   [8192,16384)  A_lo
//   [16384,24576) B_hi : 4 subtiles [32k x 32n] (64B rows, swizzled)
//   [24576,32768) B_lo
// Swizzle: chunk' = chunk ^ ((row>>1)&3)
// ---------------------------------------------------------------------------
#define BUF_BYTES 32768
#define SMEM_BYTES (2 * BUF_BYTES)
#define OFF_AHI 0
#define OFF_ALO 8192
#define OFF_BHI 16384
#define OFF_BLO 24576

__device__ __forceinline__ int swz(int row, int chunk) {
    return row * 64 + ((chunk ^ ((row >> 1) & 3)) << 4);
}

// ---------------------------------------------------------------------------
// bf16x3 HMMA GEMM, zero-conversion hot loop (cp.async of pre-split planes).
//  GATHER=true : A = (g_xhi,g_xlo)[g_tok], epilogue relu+bias -> g_hhi/g_hlo
//  GATHER=false: A = (g_hhi,g_hlo),        epilogue bias, *w -> atomicAdd out
// CTA tile 128x128, K-chunk 32, 256 threads (8 warps, 64x32 warp tiles).
// ---------------------------------------------------------------------------
template<int K_TOTAL, int B_STRIDE, bool GATHER>
__global__ __launch_bounds__(256)
void moe_mma_kernel(const __nv_bfloat16* __restrict__ Bhi,
                    const __nv_bfloat16* __restrict__ Blo,
                    const float* __restrict__ bias,
                    float* __restrict__ out) {
    const int e   = blockIdx.z;
    const int cnt = g_cnt[e];
    const int m0  = blockIdx.y * 128;
    if (m0 >= cnt) return;
    const int n0   = blockIdx.x * 128;
    const int base = g_off[e];

    extern __shared__ char smem[];
    const uint32_t sb = smem_u32(smem);
    const int t    = threadIdx.x;
    const int lane = t & 31;
    const int wid  = t >> 5;
    const int wm   = wid >> 2;     // 0..1
    const int wn   = wid & 3;      // 0..3

    // ---- cp.async staging assignments ----------------------------------
    // A: 2 threads/row: rowA = t>>1 (0..127), each thread 32B (16 elems)
    const int rowA = t >> 1;
    const int colA = (t & 1) * 16;               // element offset in k
    const int cA0  = (t & 1) * 2;                // first 16B chunk
    const __nv_bfloat16 *ahi_row, *alo_row;
    {
        int m = min(m0 + rowA, cnt - 1);
        if (GATHER) {
            size_t r = (size_t)g_tok[base + m] * D_IN;
            ahi_row = g_xhi + r; alo_row = g_xlo + r;
        } else {
            size_t r = (size_t)(base + m) * D_FF;
            ahi_row = g_hhi + r; alo_row = g_hlo + r;
        }
    }
    // B: 8 threads/row: kB = t>>3 (0..31), each thread 32B (16 elems of n)
    const int kB   = t >> 3;
    const int nb   = (t & 7) * 16;
    const int bsub = nb >> 5;                    // 32-wide n subtile
    const int cB0  = ((nb & 31) >> 3);           // 0 or 2
    const size_t wb_off = (size_t)e * K_TOTAL * B_STRIDE + n0 + nb;
    const __nv_bfloat16* bhi_p = Bhi + wb_off;
    const __nv_bfloat16* blo_p = Blo + wb_off;

    auto issue_stage = [&](int k0, int buf) {
        const uint32_t s = sb + buf * BUF_BYTES;
        // A planes
        {
            uint32_t d0 = s + OFF_AHI + swz(rowA, cA0);
            uint32_t d1 = s + OFF_AHI + swz(rowA, cA0 + 1);
            cp16(d0, ahi_row + k0 + colA);
            cp16(d1, ahi_row + k0 + colA + 8);
            cp16(d0 + (OFF_ALO - OFF_AHI), alo_row + k0 + colA);
            cp16(d1 + (OFF_ALO - OFF_AHI), alo_row + k0 + colA + 8);
        }
        // B planes
        {
            uint32_t d0 = s + OFF_BHI + bsub * 2048 + swz(kB, cB0);
            uint32_t d1 = s + OFF_BHI + bsub * 2048 + swz(kB, cB0 + 1);
            const __nv_bfloat16* sh = bhi_p + (size_t)(k0 + kB) * B_STRIDE;
            const __nv_bfloat16* sl = blo_p + (size_t)(k0 + kB) * B_STRIDE;
            cp16(d0, sh);
            cp16(d1, sh + 8);
            cp16(d0 + (OFF_BLO - OFF_BHI), sl);
            cp16(d1 + (OFF_BLO - OFF_BHI), sl + 8);
        }
        cp_commit();
    };

    float acc[4][4][4];
#pragma unroll
    for (int i = 0; i < 4; i++)
#pragma unroll
        for (int j = 0; j < 4; j++)
#pragma unroll
            for (int r = 0; r < 4; r++) acc[i][j][r] = 0.f;

    const int ml   = lane & 15;
    const int chhi = lane >> 4;

    auto mma_stage = [&](int buf) {
        const uint32_t sbuf = sb + buf * BUF_BYTES;
#pragma unroll
        for (int ks = 0; ks < 2; ks++) {
            uint32_t ah[4][4], al[4][4], bh[2][4], bl[2][4];
#pragma unroll
            for (int i = 0; i < 4; i++) {
                int m = wm * 64 + i * 16 + ml;
                int cc = (ks * 2 + chhi) ^ ((m >> 1) & 3);
                uint32_t ad = sbuf + m * 64 + cc * 16;
                ldsm4(ah[i], ad + OFF_AHI);
                ldsm4(al[i], ad + OFF_ALO);
            }
#pragma unroll
            for (int p = 0; p < 2; p++) {
                int k = ks * 16 + ml;
                int cc = (p * 2 + chhi) ^ ((k >> 1) & 3);
                uint32_t bd = sbuf + wn * 2048 + k * 64 + cc * 16;
                ldsm4t(bh[p], bd + OFF_BHI);
                ldsm4t(bl[p], bd + OFF_BLO);
            }
#pragma unroll
            for (int i = 0; i < 4; i++)
#pragma unroll
                for (int j = 0; j < 4; j++) {
                    uint32_t b0h = bh[j >> 1][(j & 1) * 2];
                    uint32_t b1h = bh[j >> 1][(j & 1) * 2 + 1];
                    uint32_t b0l = bl[j >> 1][(j & 1) * 2];
                    uint32_t b1l = bl[j >> 1][(j & 1) * 2 + 1];
                    mma16816(acc[i][j], ah[i], b0h, b1h);   // hi*hi
                    mma16816(acc[i][j], ah[i], b0l, b1l);   // hi*lo
                    mma16816(acc[i][j], al[i], b0h, b1h);   // lo*hi
                }
        }
    };

    // ---- pipelined main loop (cp.async double buffer) -------------------
    const int NCH = K_TOTAL / 32;
    issue_stage(0, 0);
    for (int ch = 0; ch < NCH; ch++) {
        if (ch + 1 < NCH) {
            issue_stage((ch + 1) * 32, (ch + 1) & 1);
            cp_wait<1>();
        } else {
            cp_wait<0>();
        }
        __syncthreads();
        mma_stage(ch & 1);
        __syncthreads();
    }

    // ---- epilogue -------------------------------------------------------
    const float* be = bias + (size_t)e * B_STRIDE;
#pragma unroll
    for (int i = 0; i < 4; i++) {
        int mA = m0 + wm * 64 + i * 16 + (lane >> 2);
#pragma unroll
        for (int half = 0; half < 2; half++) {     // rows mA and mA+8
            int m = mA + half * 8;
            if (m >= cnt) continue;
            size_t hrow = 0;
            float* op = nullptr;
            float  rw = 0.f;
            if (GATHER) {
                hrow = (size_t)(base + m) * D_FF;
            } else {
                op = out + (size_t)g_tok[base + m] * D_IN;
                rw = g_pw[base + m];
            }
#pragma unroll
            for (int j = 0; j < 4; j++) {
                int n = n0 + wn * 32 + j * 8 + (lane & 3) * 2;
                float v0 = acc[i][j][half * 2 + 0] + be[n];
                float v1 = acc[i][j][half * 2 + 1] + be[n + 1];
                if (GATHER) {
                    v0 = fmaxf(v0, 0.f); v1 = fmaxf(v1, 0.f);
                    __nv_bfloat16 h0 = __float2bfloat16(v0);
                    __nv_bfloat16 h1 = __float2bfloat16(v1);
                    __nv_bfloat16 l0 = __float2bfloat16(v0 - __bfloat162float(h0));
                    __nv_bfloat16 l1 = __float2bfloat16(v1 - __bfloat162float(h1));
                    uint32_t hp = ((uint32_t)__bfloat16_as_ushort(h1) << 16)
                                | __bfloat16_as_ushort(h0);
                    uint32_t lp = ((uint32_t)__bfloat16_as_ushort(l1) << 16)
                                | __bfloat16_as_ushort(l0);
                    *(uint32_t*)(g_hhi + hrow + n) = hp;
                    *(uint32_t*)(g_hlo + hrow + n) = lp;
                } else {
                    atomicAdd(&op[n],     rw * v0);
                    atomicAdd(&op[n + 1], rw * v1);
                }
            }
        }
    }
}

// ---------------------------------------------------------------------------
// Pre-split: fp32 array -> hi/lo bf16 planes (vectorized, grid-stride)
// ---------------------------------------------------------------------------
__global__ void split_kernel(const float* __restrict__ src,
                             __nv_bfloat16* __restrict__ hi,
                             __nv_bfloat16* __restrict__ lo, int n4) {
    int i = blockIdx.x * blockDim.x + threadIdx.x;
    for (; i < n4; i += gridDim.x * blockDim.x) {
        float4 v = ((const float4*)src)[i];
        uint2 h, l; bf16_split4(v, h, l);
        ((uint2*)hi)[i] = h;
        ((uint2*)lo)[i] = l;
    }
}

// ---------------------------------------------------------------------------
// Router / packing (unchanged)
// ---------------------------------------------------------------------------
__global__ void zero_counts_kernel() {
    int i = threadIdx.x;
    if (i < NE) { g_cnt[i] = 0; g_fill[i] = 0; }
}

__global__ void router_kernel(const float* __restrict__ x,
                              const float* __restrict__ Wr,
                              const float* __restrict__ br) {
    int gw   = (blockIdx.x * blockDim.x + threadIdx.x) >> 5;
    int lane = threadIdx.x & 31;
    if (gw >= T_TOK) return;

    const float* xr = x + (size_t)gw * D_IN;
    float acc[NE];
#pragma unroll
    for (int e = 0; e < NE; e++) acc[e] = 0.f;

    for (int d = lane; d < D_IN; d += 32) {
        float xv = xr[d];
        float4 a = *(const float4*)(Wr + d * NE);
        float4 b = *(const float4*)(Wr + d * NE + 4);
        acc[0] += xv * a.x; acc[1] += xv * a.y; acc[2] += xv * a.z; acc[3] += xv * a.w;
        acc[4] += xv * b.x; acc[5] += xv * b.y; acc[6] += xv * b.z; acc[7] += xv * b.w;
    }
#pragma unroll
    for (int e = 0; e < NE; e++) {
#pragma unroll
        for (int o = 16; o > 0; o >>= 1)
            acc[e] += __shfl_xor_sync(0xffffffffu, acc[e], o);
    }
    if (lane == 0) {
        float lg[NE];
#pragma unroll
        for (int e = 0; e < NE; e++) lg[e] = acc[e] + br[e];
        int i0 = 0;
#pragma unroll
        for (int e = 1; e < NE; e++) if (lg[e] > lg[i0]) i0 = e;
        int i1 = (i0 == 0) ? 1 : 0;
#pragma unroll
        for (int e = 0; e < NE; e++) if (e != i0 && lg[e] > lg[i1]) i1 = e;
        float ex  = expf(lg[i1] - lg[i0]);
        float inv = 1.0f / (1.0f + ex);
        g_top[2 * gw + 0] = i0;  g_top[2 * gw + 1] = i1;
        g_wt [2 * gw + 0] = inv; g_wt [2 * gw + 1] = ex * inv;
        atomicAdd(&g_cnt[i0], 1);
        atomicAdd(&g_cnt[i1], 1);
    }
}

__global__ void scan_kernel() {
    int s = 0;
    for (int e = 0; e < NE; e++) { g_off[e] = s; s += g_cnt[e]; }
}

__global__ void fill_kernel() {
    int t = blockIdx.x * blockDim.x + threadIdx.x;
    if (t >= T_TOK) return;
#pragma unroll
    for (int s = 0; s < 2; s++) {
        int e = g_top[2 * t + s];
        int p = g_off[e] + atomicAdd(&g_fill[e], 1);
        g_tok[p] = t;
        g_pw[p]  = g_wt[2 * t + s];
    }
}

// ---------------------------------------------------------------------------
// launch
// ---------------------------------------------------------------------------
extern "C" void kernel_launch(void* const* d_in, const int* in_sizes, int n_in,
                              void* d_out, int out_size) {
    const float* x   = (const float*)d_in[0];
    const float* Wr  = (const float*)d_in[1];
    const float* br  = (const float*)d_in[2];
    const float* W1  = (const float*)d_in[3];
    const float* b1  = (const float*)d_in[4];
    const float* W2  = (const float*)d_in[5];
    const float* b2  = (const float*)d_in[6];
    float*       out = (float*)d_out;

    cudaFuncSetAttribute(moe_mma_kernel<1024, 4096, true>,
                         cudaFuncAttributeMaxDynamicSharedMemorySize, SMEM_BYTES);
    cudaFuncSetAttribute(moe_mma_kernel<4096, 1024, false>,
                         cudaFuncAttributeMaxDynamicSharedMemorySize, SMEM_BYTES);

    __nv_bfloat16 *xhi, *xlo, *w1hi, *w1lo, *w2hi, *w2lo;
    cudaGetSymbolAddress((void**)&xhi,  g_xhi);
    cudaGetSymbolAddress((void**)&xlo,  g_xlo);
    cudaGetSymbolAddress((void**)&w1hi, g_w1hi);
    cudaGetSymbolAddress((void**)&w1lo, g_w1lo);
    cudaGetSymbolAddress((void**)&w2hi, g_w2hi);
    cudaGetSymbolAddress((void**)&w2lo, g_w2lo);

    cudaMemsetAsync(out, 0, (size_t)out_size * sizeof(float));
    zero_counts_kernel<<<1, 32>>>();
    router_kernel<<<T_TOK / 8, 256>>>(x, Wr, br);
    scan_kernel<<<1, 1>>>();
    fill_kernel<<<T_TOK / 256, 256>>>();

    // One-time (per launch) fp32 -> hi/lo bf16 plane splits
    split_kernel<<<1024, 256>>>(x,  xhi,  xlo,  (T_TOK * D_IN) / 4);
    split_kernel<<<2048, 256>>>(W1, w1hi, w1lo, (NE * D_IN * D_FF) / 4);
    split_kernel<<<2048, 256>>>(W2, w2hi, w2lo, (NE * D_FF * D_IN) / 4);

    // FFN1: h = relu(x_g @ W1 + b1) -> hi/lo planes; K=1024
    moe_mma_kernel<1024, 4096, true>
        <<<dim3(D_FF / 128, T_TOK / 128, NE), 256, SMEM_BYTES>>>(w1hi, w1lo, b1, out);
    // FFN2: out += w * (h @ W2 + b2); K=4096
    moe_mma_kernel<4096, 1024, false>
        <<<dim3(D_IN / 128, T_TOK / 128, NE), 256, SMEM_BYTES>>>(w2hi, w2lo, b2, out);
}